// round 14
// baseline (speedup 1.0000x reference)
#include <cuda_runtime.h>
#include <cuda_bf16.h>
#include <math.h>

#define Bc 4
#define Nc 1024
#define Hc 8
#define Dc 64
#define BSc 32
#define NBc 32
#define STOP 16
#define SCALE 0.125f
#define TOT (Bc*Nc*Hc*Dc)
#define CTOT (Bc*NBc*Hc*Dc)

// dynamic shared layout (bytes); bf16 rows pitch 72 elems = 144B (conflict-free)
#define OFF_QP 0          // qhi(4608)+qlo(4608)       | Phase A: kcmp fp32 (8192)
#define OFF_KP 9216       // khi(9216)+klo(9216)       | Phase A: q fp32 (8192)
#define OFF_VP 27648      // vhi(9216)+vlo(9216)       (Phase A: vcmp planes keys 0..31)
#define OFF_PP 46080      // phi(4608)+plo(4608)
#define SMEM_TOT 55296

typedef unsigned long long u64;
typedef unsigned int u32;

__device__ float g_kcmp[CTOT];
__device__ __nv_bfloat16 g_qhi[TOT], g_qlo[TOT], g_khi[TOT], g_klo[TOT];
__device__ __nv_bfloat16 g_vhi[TOT], g_vlo[TOT];
__device__ __nv_bfloat16 g_vchi[CTOT], g_vclo[CTOT];

__device__ __forceinline__ float siluf(float s) {
    return s / (1.f + __expf(-s));
}
__device__ __forceinline__ u64 ffma2(u64 a, u64 b, u64 c) {
    u64 d;
    asm("fma.rn.f32x2 %0, %1, %2, %3;" : "=l"(d) : "l"(a), "l"(b), "l"(c));
    return d;
}
__device__ __forceinline__ float2 u2f2(u64 u) {
    float2 f;
    asm("mov.b64 {%0, %1}, %2;" : "=f"(f.x), "=f"(f.y) : "l"(u));
    return f;
}
__device__ __forceinline__ void ldmx4(u32* a, u32 addr) {
    asm volatile("ldmatrix.sync.aligned.m8n8.x4.shared.b16 {%0,%1,%2,%3}, [%4];"
        : "=r"(a[0]), "=r"(a[1]), "=r"(a[2]), "=r"(a[3]) : "r"(addr));
}
__device__ __forceinline__ void ldmx2(u32* b, u32 addr) {
    asm volatile("ldmatrix.sync.aligned.m8n8.x2.shared.b16 {%0,%1}, [%2];"
        : "=r"(b[0]), "=r"(b[1]) : "r"(addr));
}
__device__ __forceinline__ void ldmx2t(u32* b, u32 addr) {
    asm volatile("ldmatrix.sync.aligned.m8n8.x2.trans.shared.b16 {%0,%1}, [%2];"
        : "=r"(b[0]), "=r"(b[1]) : "r"(addr));
}
__device__ __forceinline__ void mma16816(float* c, const u32* a, const u32* b) {
    asm volatile("mma.sync.aligned.m16n8k16.row.col.f32.bf16.bf16.f32 "
        "{%0,%1,%2,%3},{%4,%5,%6,%7},{%8,%9},{%0,%1,%2,%3};"
        : "+f"(c[0]), "+f"(c[1]), "+f"(c[2]), "+f"(c[3])
        : "r"(a[0]), "r"(a[1]), "r"(a[2]), "r"(a[3]), "r"(b[0]), "r"(b[1]));
}
__device__ __forceinline__ u32 pack_hi(float a, float b) {
    __nv_bfloat162 h = {__float2bfloat16(a), __float2bfloat16(b)};
    return *(u32*)&h;
}

__global__ void meanKV(const float* __restrict__ pk, const float* __restrict__ pv) {
    int blk = blockIdx.x;
    int b  = blk / (NBc*Hc);
    int kb = (blk / Hc) % NBc;
    int h  = blk % Hc;
    int d  = threadIdx.x;
    float sk = 0.f, sv = 0.f;
    int base = ((b*Nc + kb*BSc)*Hc + h)*Dc + d;
    #pragma unroll 8
    for (int j = 0; j < BSc; j++) {
        sk += pk[base + j*Hc*Dc];
        sv += pv[base + j*Hc*Dc];
    }
    int o = ((b*NBc + kb)*Hc + h)*Dc + d;
    g_kcmp[o] = sk * (1.f/BSc);
    float vc = sv * (1.f/BSc);
    __nv_bfloat16 vh = __float2bfloat16(vc);
    g_vchi[o] = vh;
    g_vclo[o] = __float2bfloat16(vc - __bfloat162float(vh));
}

__global__ void splitQKV(const float* __restrict__ pq, const float* __restrict__ pk,
                         const float* __restrict__ pv) {
    int i = blockIdx.x*256 + threadIdx.x;
    if (i < TOT) {
        float x = pq[i];
        __nv_bfloat16 h = __float2bfloat16(x);
        g_qhi[i] = h; g_qlo[i] = __float2bfloat16(x - __bfloat162float(h));
        float y = pk[i];
        __nv_bfloat16 h2 = __float2bfloat16(y);
        g_khi[i] = h2; g_klo[i] = __float2bfloat16(y - __bfloat162float(h2));
        float z = pv[i];
        __nv_bfloat16 h3 = __float2bfloat16(z);
        g_vhi[i] = h3; g_vlo[i] = __float2bfloat16(z - __bfloat162float(h3));
    }
}

// CTA = (q_block, head, batch); 4 warps. Phase A scalar fp32 (exact top-k) +
// tensor-core PV; Phase B fully tensor-core (bf16 split QK and PV).
__global__ __launch_bounds__(128, 4) void hstu_main(
    const float* __restrict__ pq, const float* __restrict__ gate_w,
    const int* __restrict__ xoff, float* __restrict__ out)
{
    extern __shared__ __align__(16) char smem[];
    float*  qsA   = (float*) (smem + OFF_KP);   // Phase A q fp32
    float4* kcmpA = (float4*)(smem + OFF_QP);   // Phase A compressed K fp32 (swizzled)
    __shared__ int list[33];
    __shared__ int lcnt;
    __shared__ unsigned unionm;
    __shared__ unsigned selm_sh[32];
    __shared__ float gsv_sh[32];

    int qb = (NBc - 1) - blockIdx.x;
    int h = blockIdx.y, b = blockIdx.z;
    int len = xoff[b+1] - xoff[b];
    if (qb * BSc >= len) return;
    int nvalid = len - qb*BSc; if (nvalid > BSc) nvalid = BSc;
    int t0 = xoff[b];
    int tid = threadIdx.x, lane = tid & 31, w = tid >> 5;

    const ulonglong2* qshU = (const ulonglong2*)qsA;
    const ulonglong2* kcU  = (const ulonglong2*)kcmpA;
    u32 sbase = (u32)__cvta_generic_to_shared(smem);
    u32 qhiA = sbase + OFF_QP, qloA = qhiA + 4608;
    u32 khiA = sbase + OFF_KP, kloA = khiA + 9216;
    u32 vhiA = sbase + OFF_VP, vloA = vhiA + 9216;
    u32 phiA = sbase + OFF_PP, ploA = phiA + 4608;

    int cst = tid & 7;            // 16B chunk within bf16 row
    int k0t = tid >> 3;           // base row (+16 per step)

    // ---- Phase A staging: q fp32, kcmp fp32 (swizzled), vcmp planes (keys 0..31) ----
    #pragma unroll
    for (int i = tid; i < 512; i += 128) {
        int r = i >> 4, c4 = i & 15;
        ((float4*)qsA)[r*16 + c4] = ((const float4*)(pq + ((b*Nc + qb*BSc + r)*Hc + h)*Dc))[c4];
        int gc = ((b*NBc + r)*Hc + h)*Dc;
        kcmpA[c4*32 + (r ^ c4)] = ((const float4*)(g_kcmp + gc))[c4];
    }
    #pragma unroll
    for (int s = 0; s < 2; s++) {
        int key = k0t + s*16;
        int g = ((b*NBc + key)*Hc + h)*Dc + cst*8;
        *(float4*)(smem + OFF_VP + key*144 + cst*16)        = *(const float4*)(g_vchi + g);
        *(float4*)(smem + OFF_VP + 9216 + key*144 + cst*16) = *(const float4*)(g_vclo + g);
    }
    if (tid == 0) unionm = 0;
    __syncthreads();

    float Cacc[2][2][4];
    #pragma unroll
    for (int mt = 0; mt < 2; mt++)
        #pragma unroll
        for (int nt = 0; nt < 2; nt++)
            #pragma unroll
            for (int e = 0; e < 4; e++) Cacc[mt][nt][e] = 0.f;
    unsigned wsel = 0;

    // ================= Phase A: scalar QK (exact), top-k, gates, compressed p ====
    {
        const float* gw = gate_w + h*Dc*3;
        float gw0a = gw[(2*lane)*3 + 0], gw0b = gw[(2*lane+1)*3 + 0];
        float gw1a = gw[(2*lane)*3 + 1], gw1b = gw[(2*lane+1)*3 + 1];

        u64 sa[8] = {0,0,0,0,0,0,0,0};
        #pragma unroll
        for (int d4 = 0; d4 < 16; d4++) {
            ulonglong2 k0 = kcU[d4*32 + (lane ^ d4)];
            #pragma unroll
            for (int qi = 0; qi < 8; qi++) {
                ulonglong2 q = qshU[(w + qi*4)*16 + d4];
                sa[qi] = ffma2(q.x, k0.x, sa[qi]);
                sa[qi] = ffma2(q.y, k0.y, sa[qi]);
            }
        }
        bool causal = (lane <= qb);
        #pragma unroll
        for (int qi = 0; qi < 8; qi++) {
            int r = w + qi*4;
            float2 fa = u2f2(sa[qi]);
            float sc = (fa.x + fa.y) * SCALE;
            bool rowok = (r < nvalid);

            float q0 = qsA[r*64 + 2*lane], q1 = qsA[r*64 + 2*lane + 1];
            float pg0 = q0*gw0a + q1*gw0b;
            float pg1 = q0*gw1a + q1*gw1b;
            #pragma unroll
            for (int off = 16; off > 0; off >>= 1) {
                pg0 += __shfl_xor_sync(0xffffffffu, pg0, off);
                pg1 += __shfl_xor_sync(0xffffffffu, pg1, off);
            }
            float gcv = 1.f / (1.f + __expf(-pg0));
            float gsvv = 1.f / (1.f + __expf(-pg1));

            float pv = (causal && rowok) ? siluf(sc) * gcv : 0.f;
            __nv_bfloat16 ph = __float2bfloat16(pv);
            *(__nv_bfloat16*)(smem + OFF_PP + r*144 + lane*2)        = ph;
            *(__nv_bfloat16*)(smem + OFF_PP + 4608 + r*144 + lane*2) =
                __float2bfloat16(pv - __bfloat162float(ph));

            unsigned sel;
            if (!rowok) {
                sel = 0u;
            } else if (qb < STOP) {
                sel = (1u << (qb + 1)) - 1u;
            } else {
                unsigned ub = __float_as_uint(sc);
                unsigned u = ((int)ub < 0) ? ~ub : (ub | 0x80000000u);
                if (!causal) u = 0u;
                unsigned T = 0u;
                #pragma unroll
                for (int bit = 31; bit >= 0; --bit) {
                    unsigned cand = T | (1u << bit);
                    unsigned bal = __ballot_sync(0xffffffffu, u >= cand);
                    if (__popc(bal) >= STOP) T = cand;
                }
                unsigned gt = __ballot_sync(0xffffffffu, u > T);
                unsigned eq = __ballot_sync(0xffffffffu, u == T);
                int need = STOP - __popc(gt);
                bool take = ((eq >> lane) & 1u) &&
                            (__popc(eq & ((1u << lane) - 1u)) < need);
                unsigned eqt = __ballot_sync(0xffffffffu, take);
                sel = gt | eqt;
            }
            wsel |= sel;
            if (lane == 0) { selm_sh[r] = sel; gsv_sh[r] = gsvv; }
        }
        __syncwarp();
        if (lane == 0) atomicOr(&unionm, wsel);
    }
    __syncthreads();
    unsigned um = unionm;
    if (tid == 0) {
        int c = 0;
        for (int kb = 0; kb <= qb; kb++)
            if ((um >> kb) & 1u) list[c++] = kb;
        lcnt = c;
    }
    // stage q bf16 planes (overwrites kcmp region; safe after barrier)
    #pragma unroll
    for (int s = 0; s < 2; s++) {
        int i = tid + s*128;
        int row = i >> 3, c = i & 7;
        int gq = ((b*Nc + qb*BSc + row)*Hc + h)*Dc + c*8;
        *(float4*)(smem + OFF_QP + row*144 + c*16)        = *(const float4*)(g_qhi + gq);
        *(float4*)(smem + OFF_QP + 4608 + row*144 + c*16) = *(const float4*)(g_qlo + gq);
    }
    __syncthreads();
    int cnt = lcnt;

    // fragment coords
    int arow = ((lane >> 3) & 1)*8 + (lane & 7);
    int acol = (lane >> 4)*8;
    int brow = lane & 7;
    int bcol = ((lane >> 3) & 1)*8;
    int l16 = lane & 15;
    int g4 = lane >> 2, t4 = lane & 3;

    // PV MMA: A = p planes, B = V planes (trans); warp w owns dims [16w, 16w+16)
    auto pv_mma = [&](int ksteps) {
        for (int ks = 0; ks < ksteps; ks++) {
            u32 aph[2][4], apl[2][4];
            #pragma unroll
            for (int mt = 0; mt < 2; mt++) {
                u32 off = (u32)(((mt*16 + arow)*72 + ks*16 + acol)*2);
                ldmx4(aph[mt], phiA + off);
                ldmx4(apl[mt], ploA + off);
            }
            #pragma unroll
            for (int nt = 0; nt < 2; nt++) {
                int n0 = 16*w + nt*8;
                u32 boff = (u32)(((ks*16 + l16)*72 + n0)*2);
                u32 bvh[2], bvl[2];
                ldmx2t(bvh, vhiA + boff);
                ldmx2t(bvl, vloA + boff);
                #pragma unroll
                for (int mt = 0; mt < 2; mt++) {
                    mma16816(Cacc[mt][nt], aph[mt], bvh);
                    mma16816(Cacc[mt][nt], aph[mt], bvl);
                    mma16816(Cacc[mt][nt], apl[mt], bvh);
                }
            }
        }
    };

    // compressed-branch PV (keys 0..31)
    pv_mma(2);
    __syncthreads();   // vcmp/p reads done before Phase B staging overwrites

    // ================= Phase B =================
    float4 rkhi[4], rklo[4];
    auto k_ld = [&](int kb0, int kb1) {
        #pragma unroll
        for (int s = 0; s < 4; s++) {
            int key = k0t + s*16;
            int kbb = (key < 32) ? (kb0*BSc + key) : (kb1*BSc + key - 32);
            int g = ((b*Nc + kbb)*Hc + h)*Dc + cst*8;
            rkhi[s] = *(const float4*)(g_khi + g);
            rklo[s] = *(const float4*)(g_klo + g);
        }
    };
    if (cnt > 0) {
        int kb0 = list[0];
        int kb1 = (1 < cnt) ? list[1] : kb0;
        k_ld(kb0, kb1);
    }

    for (int it = 0; it < cnt; it += 2) {
        int kb0 = list[it];
        bool has1 = (it + 1 < cnt);
        int kb1 = has1 ? list[it + 1] : kb0;

        // store prefetched K planes; stage V planes inline
        #pragma unroll
        for (int s = 0; s < 4; s++) {
            int key = k0t + s*16;
            *(float4*)(smem + OFF_KP + key*144 + cst*16)        = rkhi[s];
            *(float4*)(smem + OFF_KP + 9216 + key*144 + cst*16) = rklo[s];
            int kbb = (key < 32) ? (kb0*BSc + key) : (kb1*BSc + key - 32);
            int g = ((b*Nc + kbb)*Hc + h)*Dc + cst*8;
            *(float4*)(smem + OFF_VP + key*144 + cst*16)        = *(const float4*)(g_vhi + g);
            *(float4*)(smem + OFF_VP + 9216 + key*144 + cst*16) = *(const float4*)(g_vlo + g);
        }
        __syncthreads();

        if (it + 2 < cnt) {
            int nb0 = list[it + 2];
            int nb1 = (it + 3 < cnt) ? list[it + 3] : nb0;
            k_ld(nb0, nb1);
        }

        // ---- QK MMA: warp w computes keys [16w,16w+16) x rows 0..31 ----
        float C[2][2][4];
        #pragma unroll
        for (int mt = 0; mt < 2; mt++)
            #pragma unroll
            for (int nt = 0; nt < 2; nt++)
                #pragma unroll
                for (int e = 0; e < 4; e++) C[mt][nt][e] = 0.f;

        #pragma unroll
        for (int ks = 0; ks < 4; ks++) {
            u32 ahi[2][4], alo[2][4];
            #pragma unroll
            for (int mt = 0; mt < 2; mt++) {
                u32 off = (u32)(((mt*16 + arow)*72 + ks*16 + acol)*2);
                ldmx4(ahi[mt], qhiA + off);
                ldmx4(alo[mt], qloA + off);
            }
            #pragma unroll
            for (int nt = 0; nt < 2; nt++) {
                int key0 = 16*w + 8*nt;
                u32 boff = (u32)(((key0 + brow)*72 + ks*16 + bcol)*2);
                u32 bhi[2], blo[2];
                ldmx2(bhi, khiA + boff);
                ldmx2(blo, kloA + boff);
                #pragma unroll
                for (int mt = 0; mt < 2; mt++) {
                    mma16816(C[mt][nt], ahi[mt], bhi);
                    mma16816(C[mt][nt], ahi[mt], blo);
                    mma16816(C[mt][nt], alo[mt], bhi);
                }
            }
        }

        // ---- p = mask * silu(s*SCALE) * gsv -> bf16 hi/lo planes ----
        {
            int kbw = (w < 2) ? kb0 : kb1;
            bool tok = (w < 2) ? true : has1;
            bool diag = (kbw == qb);
            #pragma unroll
            for (int mt = 0; mt < 2; mt++) {
                #pragma unroll
                for (int nt = 0; nt < 2; nt++) {
                    int jl = 16*w + 8*nt + 2*t4;
                    int jt = jl & 31;
                    #pragma unroll
                    for (int hf = 0; hf < 2; hf++) {
                        int r = mt*16 + g4 + hf*8;
                        int jmax = diag ? r : 31;
                        bool selr = tok && ((selm_sh[r] >> kbw) & 1u);
                        float gv = gsv_sh[r];
                        float c0 = C[mt][nt][hf*2 + 0];
                        float c1 = C[mt][nt][hf*2 + 1];
                        float p0 = (selr && (jt     <= jmax)) ? siluf(c0*SCALE)*gv : 0.f;
                        float p1 = (selr && (jt + 1 <= jmax)) ? siluf(c1*SCALE)*gv : 0.f;
                        __nv_bfloat16 h0 = __float2bfloat16(p0);
                        __nv_bfloat16 h1 = __float2bfloat16(p1);
                        __nv_bfloat162 hi2 = {h0, h1};
                        __nv_bfloat162 lo2 = {__float2bfloat16(p0 - __bfloat162float(h0)),
                                              __float2bfloat16(p1 - __bfloat162float(h1))};
                        *(u32*)(smem + OFF_PP + r*144 + jl*2)        = *(u32*)&hi2;
                        *(u32*)(smem + OFF_PP + 4608 + r*144 + jl*2) = *(u32*)&lo2;
                    }
                }
            }
        }
        __syncthreads();   // p + V planes visible to all warps

        // ---- PV MMA over 64 keys ----
        pv_mma(4);
        __syncthreads();   // PV reads done before next staging
    }

    // ================= Output from C fragments =================
    #pragma unroll
    for (int mt = 0; mt < 2; mt++) {
        #pragma unroll
        for (int hf = 0; hf < 2; hf++) {
            int r = mt*16 + g4 + hf*8;
            if (r >= nvalid) continue;
            int o = ((t0 + qb*BSc + r)*Hc + h)*Dc;
            #pragma unroll
            for (int nt = 0; nt < 2; nt++) {
                int d = 16*w + nt*8 + 2*t4;
                float2 o2 = {Cacc[mt][nt][hf*2], Cacc[mt][nt][hf*2 + 1]};
                *(float2*)(out + o + d) = o2;
            }
        }
    }
}

extern "C" void kernel_launch(void* const* d_in, const int* in_sizes, int n_in,
                              void* d_out, int out_size) {
    const float* pq   = (const float*)d_in[4];
    const float* pk   = (const float*)d_in[5];
    const float* pv   = (const float*)d_in[6];
    const int*   xoff = (const int*)d_in[7];
    const float* gw   = (const float*)d_in[8];
    float* out = (float*)d_out;

    static int configured = 0;
    if (!configured) {
        cudaFuncSetAttribute(hstu_main,
                             cudaFuncAttributeMaxDynamicSharedMemorySize, SMEM_TOT);
        configured = 1;
    }

    meanKV<<<Bc*NBc*Hc, 64>>>(pk, pv);
    splitQKV<<<TOT/256, 256>>>(pq, pk, pv);
    dim3 grid(NBc, Hc, Bc);
    hstu_main<<<grid, 128, SMEM_TOT>>>(pq, gw, xoff, out);
}

// round 15
// speedup vs baseline: 1.1856x; 1.1856x over previous
#include <cuda_runtime.h>
#include <cuda_bf16.h>
#include <math.h>

#define Bc 4
#define Nc 1024
#define Hc 8
#define Dc 64
#define BSc 32
#define NBc 32
#define STOP 16
#define SCALE 0.125f
#define TOT (Bc*Nc*Hc*Dc)
#define CTOT (Bc*NBc*Hc*Dc)

// dynamic shared layout (bytes); bf16 rows pitch 72 elems = 144B (conflict-free)
#define OFF_QP 0          // Phase B: qhi(4608)+qlo(4608); Phase A: kcmp fp32 (8192)
#define OFF_KP 9216       // Phase B: khi(9216)+klo(9216); Phase A: q fp32 (8192)
#define OFF_V  27648      // vb4 fp32 (16384)
#define OFF_P  44032      // p_sh 32x64 fp32 (8192)
#define SMEM_TOT 52224

typedef unsigned long long u64;
typedef unsigned int u32;

__device__ float g_kcmp[CTOT];
__device__ float g_vcmp[CTOT];
__device__ __nv_bfloat16 g_khi[TOT], g_klo[TOT];

__device__ __forceinline__ float siluf(float s) {
    return s / (1.f + __expf(-s));
}
__device__ __forceinline__ u64 ffma2(u64 a, u64 b, u64 c) {
    u64 d;
    asm("fma.rn.f32x2 %0, %1, %2, %3;" : "=l"(d) : "l"(a), "l"(b), "l"(c));
    return d;
}
__device__ __forceinline__ u64 dup2(float x) {
    u64 r;
    asm("mov.b64 %0, {%1, %1};" : "=l"(r) : "f"(x));
    return r;
}
__device__ __forceinline__ float2 u2f2(u64 u) {
    float2 f;
    asm("mov.b64 {%0, %1}, %2;" : "=f"(f.x), "=f"(f.y) : "l"(u));
    return f;
}
__device__ __forceinline__ void ldmx4(u32* a, u32 addr) {
    asm volatile("ldmatrix.sync.aligned.m8n8.x4.shared.b16 {%0,%1,%2,%3}, [%4];"
        : "=r"(a[0]), "=r"(a[1]), "=r"(a[2]), "=r"(a[3]) : "r"(addr));
}
__device__ __forceinline__ void ldmx2(u32* b, u32 addr) {
    asm volatile("ldmatrix.sync.aligned.m8n8.x2.shared.b16 {%0,%1}, [%2];"
        : "=r"(b[0]), "=r"(b[1]) : "r"(addr));
}
__device__ __forceinline__ void mma16816(float* c, const u32* a, const u32* b) {
    asm volatile("mma.sync.aligned.m16n8k16.row.col.f32.bf16.bf16.f32 "
        "{%0,%1,%2,%3},{%4,%5,%6,%7},{%8,%9},{%0,%1,%2,%3};"
        : "+f"(c[0]), "+f"(c[1]), "+f"(c[2]), "+f"(c[3])
        : "r"(a[0]), "r"(a[1]), "r"(a[2]), "r"(a[3]), "r"(b[0]), "r"(b[1]));
}

// fused preprocessing: blocks [0,256) do block-mean K/V; blocks [256,8448) split K
__global__ void prep(const float* __restrict__ pk, const float* __restrict__ pv) {
    int blk = blockIdx.x;
    if (blk < 256) {
        int o = blk*256 + threadIdx.x;       // [b][kb][h][d] flat, o < CTOT
        int d  = o & 63;
        int h  = (o >> 6) & 7;
        int kb = (o >> 9) & 31;
        int b  = o >> 14;
        float sk = 0.f, sv = 0.f;
        int base = ((b*Nc + kb*BSc)*Hc + h)*Dc + d;
        #pragma unroll 8
        for (int j = 0; j < BSc; j++) {
            sk += pk[base + j*Hc*Dc];
            sv += pv[base + j*Hc*Dc];
        }
        g_kcmp[o] = sk * (1.f/BSc);
        g_vcmp[o] = sv * (1.f/BSc);
    } else {
        int i = (blk - 256)*256 + threadIdx.x;   // i < TOT
        float y = pk[i];
        __nv_bfloat16 h2 = __float2bfloat16(y);
        g_khi[i] = h2;
        g_klo[i] = __float2bfloat16(y - __bfloat162float(h2));
    }
}

// CTA = (q_block, head, batch); 4 warps. Phase A scalar fp32 (exact top-k, gates,
// compressed PV). Phase B: QK on bf16-split MMA, PV scalar fp32 with per-warp skip.
__global__ __launch_bounds__(128, 4) void hstu_main(
    const float* __restrict__ pq, const float* __restrict__ pvv,
    const float* __restrict__ gate_w, const int* __restrict__ xoff,
    float* __restrict__ out)
{
    extern __shared__ __align__(16) char smem[];
    float*  qsA   = (float*) (smem + OFF_KP);   // Phase A q fp32
    float4* kcmpA = (float4*)(smem + OFF_QP);   // Phase A compressed K fp32 (swizzled)
    float4* vb4   = (float4*)(smem + OFF_V);
    float*  p_sh  = (float*) (smem + OFF_P);
    __shared__ int list[33];
    __shared__ int lcnt;
    __shared__ unsigned unionm;
    __shared__ unsigned selm_sh[32];
    __shared__ float gsv_sh[32];

    int qb = (NBc - 1) - blockIdx.x;
    int h = blockIdx.y, b = blockIdx.z;
    int len = xoff[b+1] - xoff[b];
    if (qb * BSc >= len) return;
    int nvalid = len - qb*BSc; if (nvalid > BSc) nvalid = BSc;
    int t0 = xoff[b];
    int tid = threadIdx.x, lane = tid & 31, w = tid >> 5;

    const ulonglong2* qshU = (const ulonglong2*)qsA;
    const ulonglong2* kcU  = (const ulonglong2*)kcmpA;
    const u64*        vbU  = (const u64*)vb4;
    const float4*     p4   = (const float4*)p_sh;
    u32 sbase = (u32)__cvta_generic_to_shared(smem);
    u32 qhiA = sbase + OFF_QP, qloA = qhiA + 4608;
    u32 khiA = sbase + OFF_KP, kloA = khiA + 9216;

    // ---- Phase A staging: q fp32, kcmp fp32 (swizzled), vcmp fp32 ----
    #pragma unroll
    for (int i = tid; i < 512; i += 128) {
        int r = i >> 4, c4 = i & 15;
        ((float4*)qsA)[r*16 + c4] = ((const float4*)(pq + ((b*Nc + qb*BSc + r)*Hc + h)*Dc))[c4];
        int gc = ((b*NBc + r)*Hc + h)*Dc;
        kcmpA[c4*32 + (r ^ c4)] = ((const float4*)(g_kcmp + gc))[c4];
        vb4[r*16 + c4]          = ((const float4*)(g_vcmp + gc))[c4];
    }
    if (tid == 0) unionm = 0;
    __syncthreads();

    u64 acc[8] = {0,0,0,0,0,0,0,0};
    unsigned wsel = 0;

    // ================= Phase A (scalar fp32, exact top-k) =================
    {
        const float* gw = gate_w + h*Dc*3;
        float gw0a = gw[(2*lane)*3 + 0], gw0b = gw[(2*lane+1)*3 + 0];
        float gw1a = gw[(2*lane)*3 + 1], gw1b = gw[(2*lane+1)*3 + 1];

        u64 sa[8] = {0,0,0,0,0,0,0,0};
        #pragma unroll
        for (int d4 = 0; d4 < 16; d4++) {
            ulonglong2 k0 = kcU[d4*32 + (lane ^ d4)];
            #pragma unroll
            for (int qi = 0; qi < 8; qi++) {
                ulonglong2 q = qshU[(w + qi*4)*16 + d4];
                sa[qi] = ffma2(q.x, k0.x, sa[qi]);
                sa[qi] = ffma2(q.y, k0.y, sa[qi]);
            }
        }
        bool causal = (lane <= qb);
        #pragma unroll
        for (int qi = 0; qi < 8; qi++) {
            int r = w + qi*4;
            float2 fa = u2f2(sa[qi]);
            float sc = (fa.x + fa.y) * SCALE;
            bool rowok = (r < nvalid);

            float q0 = qsA[r*64 + 2*lane], q1 = qsA[r*64 + 2*lane + 1];
            float pg0 = q0*gw0a + q1*gw0b;
            float pg1 = q0*gw1a + q1*gw1b;
            #pragma unroll
            for (int off = 16; off > 0; off >>= 1) {
                pg0 += __shfl_xor_sync(0xffffffffu, pg0, off);
                pg1 += __shfl_xor_sync(0xffffffffu, pg1, off);
            }
            float gcv = 1.f / (1.f + __expf(-pg0));
            float gsvv = 1.f / (1.f + __expf(-pg1));

            p_sh[r*64 + lane] = (causal && rowok) ? siluf(sc) * gcv : 0.f;

            unsigned sel;
            if (!rowok) {
                sel = 0u;
            } else if (qb < STOP) {
                sel = (1u << (qb + 1)) - 1u;
            } else {
                unsigned ub = __float_as_uint(sc);
                unsigned u = ((int)ub < 0) ? ~ub : (ub | 0x80000000u);
                if (!causal) u = 0u;
                unsigned T = 0u;
                #pragma unroll
                for (int bit = 31; bit >= 0; --bit) {
                    unsigned cand = T | (1u << bit);
                    unsigned bal = __ballot_sync(0xffffffffu, u >= cand);
                    if (__popc(bal) >= STOP) T = cand;
                }
                unsigned gt = __ballot_sync(0xffffffffu, u > T);
                unsigned eq = __ballot_sync(0xffffffffu, u == T);
                int need = STOP - __popc(gt);
                bool take = ((eq >> lane) & 1u) &&
                            (__popc(eq & ((1u << lane) - 1u)) < need);
                unsigned eqt = __ballot_sync(0xffffffffu, take);
                sel = gt | eqt;
            }
            wsel |= sel;
            if (lane == 0) { selm_sh[r] = sel; gsv_sh[r] = gsvv; }
        }
        __syncwarp();
        if (lane == 0) atomicOr(&unionm, wsel);

        // compressed PV (keys 0..qb)
        int j4hi = qb >> 2;
        for (int j4 = 0; j4 <= j4hi; j4++) {
            u64 v[4];
            #pragma unroll
            for (int jj = 0; jj < 4; jj++) v[jj] = vbU[(j4*4 + jj)*32 + lane];
            #pragma unroll
            for (int qi = 0; qi < 8; qi++) {
                float4 pb = p4[(w + qi*4)*16 + j4];
                acc[qi] = ffma2(dup2(pb.x), v[0], acc[qi]);
                acc[qi] = ffma2(dup2(pb.y), v[1], acc[qi]);
                acc[qi] = ffma2(dup2(pb.z), v[2], acc[qi]);
                acc[qi] = ffma2(dup2(pb.w), v[3], acc[qi]);
            }
        }
    }
    __syncthreads();   // Phase A reads of kcmp/q done
    unsigned um = unionm;
    if (tid == 0) {
        int c = 0;
        for (int kb = 0; kb <= qb; kb++)
            if ((um >> kb) & 1u) list[c++] = kb;
        lcnt = c;
    }

    // ---- derive q bf16 planes locally from qsA (overwrites kcmp region) ----
    #pragma unroll
    for (int s = 0; s < 2; s++) {
        int i = tid + s*128;
        int row = i >> 3, c = i & 7;
        const float* qr = qsA + row*64 + c*8;
        u32 hw[4], lw[4];
        #pragma unroll
        for (int e = 0; e < 4; e++) {
            float x0 = qr[2*e], x1 = qr[2*e + 1];
            __nv_bfloat16 h0 = __float2bfloat16(x0), h1 = __float2bfloat16(x1);
            __nv_bfloat162 hh2 = {h0, h1};
            hw[e] = *(u32*)&hh2;
            __nv_bfloat162 ll2 = {__float2bfloat16(x0 - __bfloat162float(h0)),
                                  __float2bfloat16(x1 - __bfloat162float(h1))};
            lw[e] = *(u32*)&ll2;
        }
        *(uint4*)(smem + OFF_QP + row*144 + c*16)        = *(uint4*)hw;
        *(uint4*)(smem + OFF_QP + 4608 + row*144 + c*16) = *(uint4*)lw;
    }
    __syncthreads();
    int cnt = lcnt;

    // ================= Phase B =================
    int cst = tid & 7;            // K chunk (8 bf16 = 16B)
    int k0t = tid >> 3;           // base key (+16 per sweep)
    float4 rkhi[4], rklo[4];      // prefetched K pair planes

    auto k_ld = [&](int kb0, int kb1) {
        #pragma unroll
        for (int s = 0; s < 4; s++) {
            int key = k0t + s*16;
            int kbb = (key < 32) ? (kb0*BSc + key) : (kb1*BSc + key - 32);
            int g = ((b*Nc + kbb)*Hc + h)*Dc + cst*8;
            rkhi[s] = *(const float4*)(g_khi + g);
            rklo[s] = *(const float4*)(g_klo + g);
        }
    };

    if (cnt > 0) {
        int kb0 = list[0];
        int kb1 = (1 < cnt) ? list[1] : kb0;
        k_ld(kb0, kb1);
    }

    int r0s = tid >> 4, c4s = tid & 15;   // V staging coords
    int arow = ((lane >> 3) & 1)*8 + (lane & 7);
    int acol = (lane >> 4)*8;
    int brow = lane & 7;
    int bcol = ((lane >> 3) & 1)*8;
    int g4 = lane >> 2, t4 = lane & 3;

    for (int it = 0; it < cnt; it += 2) {
        int kb0 = list[it];
        bool has1 = (it + 1 < cnt);
        int kb1 = has1 ? list[it + 1] : kb0;

        // store prefetched K planes; stage V inline
        #pragma unroll
        for (int s = 0; s < 4; s++) {
            int key = k0t + s*16;
            *(float4*)(smem + OFF_KP + key*144 + cst*16)        = rkhi[s];
            *(float4*)(smem + OFF_KP + 9216 + key*144 + cst*16) = rklo[s];
        }
        #pragma unroll
        for (int s = 0; s < 4; s++) {
            int row = r0s + s*8;
            vb4[row*16 + c4s]        = ((const float4*)(pvv + ((b*Nc + kb0*BSc + row)*Hc + h)*Dc))[c4s];
            vb4[(row + 32)*16 + c4s] = ((const float4*)(pvv + ((b*Nc + kb1*BSc + row)*Hc + h)*Dc))[c4s];
        }
        __syncthreads();

        // prefetch next pair's K planes
        if (it + 2 < cnt) {
            int nb0 = list[it + 2];
            int nb1 = (it + 3 < cnt) ? list[it + 3] : nb0;
            k_ld(nb0, nb1);
        }

        // ---- QK via bf16-split MMA: warp w computes keys [16w,16w+16) x rows 0..31 ----
        float C[2][2][4];
        #pragma unroll
        for (int mt = 0; mt < 2; mt++)
            #pragma unroll
            for (int nt = 0; nt < 2; nt++)
                #pragma unroll
                for (int e = 0; e < 4; e++) C[mt][nt][e] = 0.f;

        #pragma unroll
        for (int ks = 0; ks < 4; ks++) {
            u32 ahi[2][4], alo[2][4];
            #pragma unroll
            for (int mt = 0; mt < 2; mt++) {
                u32 off = (u32)(((mt*16 + arow)*72 + ks*16 + acol)*2);
                ldmx4(ahi[mt], qhiA + off);
                ldmx4(alo[mt], qloA + off);
            }
            #pragma unroll
            for (int nt = 0; nt < 2; nt++) {
                int key0 = 16*w + 8*nt;
                u32 boff = (u32)(((key0 + brow)*72 + ks*16 + bcol)*2);
                u32 bhi[2], blo[2];
                ldmx2(bhi, khiA + boff);
                ldmx2(blo, kloA + boff);
                #pragma unroll
                for (int mt = 0; mt < 2; mt++) {
                    mma16816(C[mt][nt], ahi[mt], bhi);
                    mma16816(C[mt][nt], ahi[mt], blo);
                    mma16816(C[mt][nt], alo[mt], bhi);
                }
            }
        }

        // ---- p = mask * silu(s*SCALE) * gsv, written to p_sh[row][key] ----
        {
            int kbw = (w < 2) ? kb0 : kb1;
            bool tok = (w < 2) ? true : has1;
            bool diag = (kbw == qb);
            #pragma unroll
            for (int mt = 0; mt < 2; mt++) {
                #pragma unroll
                for (int nt = 0; nt < 2; nt++) {
                    int jl = 16*w + 8*nt + 2*t4;
                    int jt = jl & 31;
                    #pragma unroll
                    for (int hf = 0; hf < 2; hf++) {
                        int r = mt*16 + g4 + hf*8;
                        int jmax = diag ? r : 31;
                        bool selr = tok && ((selm_sh[r] >> kbw) & 1u);
                        float gv = gsv_sh[r];
                        float c0 = C[mt][nt][hf*2 + 0];
                        float c1 = C[mt][nt][hf*2 + 1];
                        float2 pp;
                        pp.x = (selr && (jt     <= jmax)) ? siluf(c0*SCALE)*gv : 0.f;
                        pp.y = (selr && (jt + 1 <= jmax)) ? siluf(c1*SCALE)*gv : 0.f;
                        *(float2*)&p_sh[r*64 + jl] = pp;
                    }
                }
            }
        }
        __syncthreads();   // p from all warps visible

        // ---- PV scalar fp32 (per-warp skip) ----
        bool need0 = (wsel >> kb0) & 1u;
        bool need1 = has1 && ((wsel >> kb1) & 1u);
        if (need0) {
            #pragma unroll
            for (int j4 = 0; j4 < 8; j4++) {
                u64 v[4];
                #pragma unroll
                for (int jj = 0; jj < 4; jj++) v[jj] = vbU[(j4*4 + jj)*32 + lane];
                #pragma unroll
                for (int qi = 0; qi < 8; qi++) {
                    float4 pb = p4[(w + qi*4)*16 + j4];
                    acc[qi] = ffma2(dup2(pb.x), v[0], acc[qi]);
                    acc[qi] = ffma2(dup2(pb.y), v[1], acc[qi]);
                    acc[qi] = ffma2(dup2(pb.z), v[2], acc[qi]);
                    acc[qi] = ffma2(dup2(pb.w), v[3], acc[qi]);
                }
            }
        }
        if (need1) {
            #pragma unroll
            for (int j4 = 8; j4 < 16; j4++) {
                u64 v[4];
                #pragma unroll
                for (int jj = 0; jj < 4; jj++) v[jj] = vbU[(j4*4 + jj)*32 + lane];
                #pragma unroll
                for (int qi = 0; qi < 8; qi++) {
                    float4 pb = p4[(w + qi*4)*16 + j4];
                    acc[qi] = ffma2(dup2(pb.x), v[0], acc[qi]);
                    acc[qi] = ffma2(dup2(pb.y), v[1], acc[qi]);
                    acc[qi] = ffma2(dup2(pb.z), v[2], acc[qi]);
                    acc[qi] = ffma2(dup2(pb.w), v[3], acc[qi]);
                }
            }
        }
        __syncthreads();   // all PV reads done before next staging
    }

    // ================= Output (already gated) =================
    #pragma unroll
    for (int qi = 0; qi < 8; qi++) {
        int r = w + qi*4;
        if (r >= nvalid) continue;   // warp-uniform
        float2 o2 = u2f2(acc[qi]);
        int n = qb*BSc + r;
        int o = ((t0 + n)*Hc + h)*Dc;
        *((float2*)(out + o) + lane) = o2;
    }
}

extern "C" void kernel_launch(void* const* d_in, const int* in_sizes, int n_in,
                              void* d_out, int out_size) {
    const float* pq   = (const float*)d_in[4];
    const float* pk   = (const float*)d_in[5];
    const float* pv   = (const float*)d_in[6];
    const int*   xoff = (const int*)d_in[7];
    const float* gw   = (const float*)d_in[8];
    float* out = (float*)d_out;

    static int configured = 0;
    if (!configured) {
        cudaFuncSetAttribute(hstu_main,
                             cudaFuncAttributeMaxDynamicSharedMemorySize, SMEM_TOT);
        configured = 1;
    }

    prep<<<256 + TOT/256, 256>>>(pk, pv);
    dim3 grid(NBc, Hc, Bc);
    hstu_main<<<grid, 128, SMEM_TOT>>>(pq, pv, gw, xoff, out);
}

// round 16
// speedup vs baseline: 1.2239x; 1.0323x over previous
#include <cuda_runtime.h>
#include <cuda_bf16.h>
#include <math.h>

#define Bc 4
#define Nc 1024
#define Hc 8
#define Dc 64
#define BSc 32
#define NBc 32
#define STOP 16
#define SCALE 0.125f
#define TOT (Bc*Nc*Hc*Dc)
#define CTOT (Bc*NBc*Hc*Dc)
#define PPITCH 68   // p_sh row pitch in floats (17x16B -> 4-row reads conflict-free)

// dynamic shared layout (bytes); bf16 rows pitch 72 elems = 144B
#define OFF_QP 0          // Phase B: qhi(4608)+qlo(4608); Phase A: kcmp fp32 (8192)
#define OFF_KP 9216       // Phase B: khi(9216)+klo(9216); Phase A: q fp32 (8192)
#define OFF_V  27648      // vb4 fp32 (16384)
#define OFF_P  44032      // p_sh 32xPPITCH fp32 (8704)
#define SMEM_TOT 52736

typedef unsigned long long u64;
typedef unsigned int u32;

__device__ float g_kcmp[CTOT];
__device__ float g_vcmp[CTOT];
__device__ __nv_bfloat16 g_khi[TOT], g_klo[TOT];

__device__ __forceinline__ float siluf(float s) {
    return s / (1.f + __expf(-s));
}
__device__ __forceinline__ u64 ffma2(u64 a, u64 b, u64 c) {
    u64 d;
    asm("fma.rn.f32x2 %0, %1, %2, %3;" : "=l"(d) : "l"(a), "l"(b), "l"(c));
    return d;
}
__device__ __forceinline__ u64 dup2(float x) {
    u64 r;
    asm("mov.b64 %0, {%1, %1};" : "=l"(r) : "f"(x));
    return r;
}
__device__ __forceinline__ float2 u2f2(u64 u) {
    float2 f;
    asm("mov.b64 {%0, %1}, %2;" : "=f"(f.x), "=f"(f.y) : "l"(u));
    return f;
}
__device__ __forceinline__ void ldmx4(u32* a, u32 addr) {
    asm volatile("ldmatrix.sync.aligned.m8n8.x4.shared.b16 {%0,%1,%2,%3}, [%4];"
        : "=r"(a[0]), "=r"(a[1]), "=r"(a[2]), "=r"(a[3]) : "r"(addr));
}
__device__ __forceinline__ void ldmx2(u32* b, u32 addr) {
    asm volatile("ldmatrix.sync.aligned.m8n8.x2.shared.b16 {%0,%1}, [%2];"
        : "=r"(b[0]), "=r"(b[1]) : "r"(addr));
}
__device__ __forceinline__ void mma16816(float* c, const u32* a, const u32* b) {
    asm volatile("mma.sync.aligned.m16n8k16.row.col.f32.bf16.bf16.f32 "
        "{%0,%1,%2,%3},{%4,%5,%6,%7},{%8,%9},{%0,%1,%2,%3};"
        : "+f"(c[0]), "+f"(c[1]), "+f"(c[2]), "+f"(c[3])
        : "r"(a[0]), "r"(a[1]), "r"(a[2]), "r"(a[3]), "r"(b[0]), "r"(b[1]));
}

// fused preprocessing: blocks [0,256) block-mean K/V; blocks [256,8448) split K
__global__ void prep(const float* __restrict__ pk, const float* __restrict__ pv) {
    int blk = blockIdx.x;
    if (blk < 256) {
        int o = blk*256 + threadIdx.x;
        int d  = o & 63;
        int h  = (o >> 6) & 7;
        int kb = (o >> 9) & 31;
        int b  = o >> 14;
        float sk = 0.f, sv = 0.f;
        int base = ((b*Nc + kb*BSc)*Hc + h)*Dc + d;
        #pragma unroll 8
        for (int j = 0; j < BSc; j++) {
            sk += pk[base + j*Hc*Dc];
            sv += pv[base + j*Hc*Dc];
        }
        g_kcmp[o] = sk * (1.f/BSc);
        g_vcmp[o] = sv * (1.f/BSc);
    } else {
        int i = (blk - 256)*256 + threadIdx.x;
        float y = pk[i];
        __nv_bfloat16 h2 = __float2bfloat16(y);
        g_khi[i] = h2;
        g_klo[i] = __float2bfloat16(y - __bfloat162float(h2));
    }
}

// CTA = (q_block, head, batch); 4 warps. Phase A scalar fp32 (exact top-k, gates).
// Phase B: QK bf16-split MMA; PV dim-split scalar fp32 (warp w owns dims [16w,16w+16),
// lane = (row-group rg = lane>>3, dim-pair dp = lane&7), acc[k] = row rg+4k).
__global__ __launch_bounds__(128, 4) void hstu_main(
    const float* __restrict__ pq, const float* __restrict__ pvv,
    const float* __restrict__ gate_w, const int* __restrict__ xoff,
    float* __restrict__ out)
{
    extern __shared__ __align__(16) char smem[];
    float*  qsA   = (float*) (smem + OFF_KP);
    float4* kcmpA = (float4*)(smem + OFF_QP);
    float4* vb4   = (float4*)(smem + OFF_V);
    float*  p_sh  = (float*) (smem + OFF_P);
    __shared__ int list[33];
    __shared__ int lcnt;
    __shared__ unsigned unionm;
    __shared__ unsigned selm_sh[32];
    __shared__ float gsv_sh[32];

    int qb = (NBc - 1) - blockIdx.x;
    int h = blockIdx.y, b = blockIdx.z;
    int len = xoff[b+1] - xoff[b];
    if (qb * BSc >= len) return;
    int nvalid = len - qb*BSc; if (nvalid > BSc) nvalid = BSc;
    int t0 = xoff[b];
    int tid = threadIdx.x, lane = tid & 31, w = tid >> 5;
    int dp8 = lane & 7, rg = lane >> 3;

    const ulonglong2* qshU = (const ulonglong2*)qsA;
    const ulonglong2* kcU  = (const ulonglong2*)kcmpA;
    const u64*        vbU  = (const u64*)vb4;
    const float4*     p4   = (const float4*)p_sh;
    u32 sbase = (u32)__cvta_generic_to_shared(smem);
    u32 qhiA = sbase + OFF_QP, qloA = qhiA + 4608;
    u32 khiA = sbase + OFF_KP, kloA = khiA + 9216;

    // ---- Phase A staging ----
    #pragma unroll
    for (int i = tid; i < 512; i += 128) {
        int r = i >> 4, c4 = i & 15;
        ((float4*)qsA)[r*16 + c4] = ((const float4*)(pq + ((b*Nc + qb*BSc + r)*Hc + h)*Dc))[c4];
        int gc = ((b*NBc + r)*Hc + h)*Dc;
        kcmpA[c4*32 + (r ^ c4)] = ((const float4*)(g_kcmp + gc))[c4];
        vb4[r*16 + c4]          = ((const float4*)(g_vcmp + gc))[c4];
    }
    if (tid == 0) unionm = 0;
    __syncthreads();

    u64 acc[8] = {0,0,0,0,0,0,0,0};
    unsigned wsel = 0;

    // ================= Phase A (scalar fp32, exact top-k) =================
    {
        const float* gw = gate_w + h*Dc*3;
        float gw0a = gw[(2*lane)*3 + 0], gw0b = gw[(2*lane+1)*3 + 0];
        float gw1a = gw[(2*lane)*3 + 1], gw1b = gw[(2*lane+1)*3 + 1];

        u64 sa[8] = {0,0,0,0,0,0,0,0};
        #pragma unroll
        for (int d4 = 0; d4 < 16; d4++) {
            ulonglong2 k0 = kcU[d4*32 + (lane ^ d4)];
            #pragma unroll
            for (int qi = 0; qi < 8; qi++) {
                ulonglong2 q = qshU[(w + qi*4)*16 + d4];
                sa[qi] = ffma2(q.x, k0.x, sa[qi]);
                sa[qi] = ffma2(q.y, k0.y, sa[qi]);
            }
        }
        bool causal = (lane <= qb);
        #pragma unroll
        for (int qi = 0; qi < 8; qi++) {
            int r = w + qi*4;
            float2 fa = u2f2(sa[qi]);
            float sc = (fa.x + fa.y) * SCALE;
            bool rowok = (r < nvalid);

            float q0 = qsA[r*64 + 2*lane], q1 = qsA[r*64 + 2*lane + 1];
            float pg0 = q0*gw0a + q1*gw0b;
            float pg1 = q0*gw1a + q1*gw1b;
            #pragma unroll
            for (int off = 16; off > 0; off >>= 1) {
                pg0 += __shfl_xor_sync(0xffffffffu, pg0, off);
                pg1 += __shfl_xor_sync(0xffffffffu, pg1, off);
            }
            float gcv = 1.f / (1.f + __expf(-pg0));
            float gsvv = 1.f / (1.f + __expf(-pg1));

            p_sh[r*PPITCH + lane] = (causal && rowok) ? siluf(sc) * gcv : 0.f;

            unsigned sel;
            if (!rowok) {
                sel = 0u;
            } else if (qb < STOP) {
                sel = (1u << (qb + 1)) - 1u;
            } else {
                unsigned ub = __float_as_uint(sc);
                unsigned u = ((int)ub < 0) ? ~ub : (ub | 0x80000000u);
                if (!causal) u = 0u;
                unsigned T = 0u;
                #pragma unroll
                for (int bit = 31; bit >= 0; --bit) {
                    unsigned cand = T | (1u << bit);
                    unsigned bal = __ballot_sync(0xffffffffu, u >= cand);
                    if (__popc(bal) >= STOP) T = cand;
                }
                unsigned gt = __ballot_sync(0xffffffffu, u > T);
                unsigned eq = __ballot_sync(0xffffffffu, u == T);
                int need = STOP - __popc(gt);
                bool take = ((eq >> lane) & 1u) &&
                            (__popc(eq & ((1u << lane) - 1u)) < need);
                unsigned eqt = __ballot_sync(0xffffffffu, take);
                sel = gt | eqt;
            }
            wsel |= sel;
            if (lane == 0) { selm_sh[r] = sel; gsv_sh[r] = gsvv; }
        }
        __syncwarp();
        if (lane == 0) atomicOr(&unionm, wsel);
    }
    __syncthreads();   // p rows + selm + gsv visible to all warps

    // ---- compressed PV (dim-split; keys 0..qb) ----
    {
        int j4hi = qb >> 2;
        for (int j4 = 0; j4 <= j4hi; j4++) {
            u64 v0 = vbU[(j4*4 + 0)*32 + 8*w + dp8];
            u64 v1 = vbU[(j4*4 + 1)*32 + 8*w + dp8];
            u64 v2 = vbU[(j4*4 + 2)*32 + 8*w + dp8];
            u64 v3 = vbU[(j4*4 + 3)*32 + 8*w + dp8];
            #pragma unroll
            for (int k = 0; k < 8; k++) {
                float4 pb = p4[(rg + 4*k)*17 + j4];
                acc[k] = ffma2(dup2(pb.x), v0, acc[k]);
                acc[k] = ffma2(dup2(pb.y), v1, acc[k]);
                acc[k] = ffma2(dup2(pb.z), v2, acc[k]);
                acc[k] = ffma2(dup2(pb.w), v3, acc[k]);
            }
        }
    }
    __syncthreads();   // Phase A kcmp/q/vcmp/p reads done
    unsigned um = unionm;
    if (tid == 0) {
        int c = 0;
        for (int kb = 0; kb <= qb; kb++)
            if ((um >> kb) & 1u) list[c++] = kb;
        lcnt = c;
    }

    // ---- derive q bf16 planes locally (overwrites kcmp region) ----
    #pragma unroll
    for (int s = 0; s < 2; s++) {
        int i = tid + s*128;
        int row = i >> 3, c = i & 7;
        const float* qr = qsA + row*64 + c*8;
        u32 hw[4], lw[4];
        #pragma unroll
        for (int e = 0; e < 4; e++) {
            float x0 = qr[2*e], x1 = qr[2*e + 1];
            __nv_bfloat16 h0 = __float2bfloat16(x0), h1 = __float2bfloat16(x1);
            __nv_bfloat162 hh2 = {h0, h1};
            hw[e] = *(u32*)&hh2;
            __nv_bfloat162 ll2 = {__float2bfloat16(x0 - __bfloat162float(h0)),
                                  __float2bfloat16(x1 - __bfloat162float(h1))};
            lw[e] = *(u32*)&ll2;
        }
        *(uint4*)(smem + OFF_QP + row*144 + c*16)        = *(uint4*)hw;
        *(uint4*)(smem + OFF_QP + 4608 + row*144 + c*16) = *(uint4*)lw;
    }
    __syncthreads();
    int cnt = lcnt;

    // ================= Phase B =================
    int cst = tid & 7;
    int k0t = tid >> 3;
    float4 rkhi[4], rklo[4];

    auto k_ld = [&](int kb0, int kb1) {
        #pragma unroll
        for (int s = 0; s < 4; s++) {
            int key = k0t + s*16;
            int kbb = (key < 32) ? (kb0*BSc + key) : (kb1*BSc + key - 32);
            int g = ((b*Nc + kbb)*Hc + h)*Dc + cst*8;
            rkhi[s] = *(const float4*)(g_khi + g);
            rklo[s] = *(const float4*)(g_klo + g);
        }
    };

    if (cnt > 0) {
        int kb0 = list[0];
        int kb1 = (1 < cnt) ? list[1] : kb0;
        k_ld(kb0, kb1);
    }

    int r0s = tid >> 4, c4s = tid & 15;
    int arow = ((lane >> 3) & 1)*8 + (lane & 7);
    int acol = (lane >> 4)*8;
    int brow = lane & 7;
    int bcol = ((lane >> 3) & 1)*8;
    int g4 = lane >> 2, t4 = lane & 3;

    for (int it = 0; it < cnt; it += 2) {
        int kb0 = list[it];
        bool has1 = (it + 1 < cnt);
        int kb1 = has1 ? list[it + 1] : kb0;

        // store prefetched K planes; stage V inline
        #pragma unroll
        for (int s = 0; s < 4; s++) {
            int key = k0t + s*16;
            *(float4*)(smem + OFF_KP + key*144 + cst*16)        = rkhi[s];
            *(float4*)(smem + OFF_KP + 9216 + key*144 + cst*16) = rklo[s];
        }
        #pragma unroll
        for (int s = 0; s < 4; s++) {
            int row = r0s + s*8;
            vb4[row*16 + c4s]        = ((const float4*)(pvv + ((b*Nc + kb0*BSc + row)*Hc + h)*Dc))[c4s];
            vb4[(row + 32)*16 + c4s] = ((const float4*)(pvv + ((b*Nc + kb1*BSc + row)*Hc + h)*Dc))[c4s];
        }
        __syncthreads();

        if (it + 2 < cnt) {
            int nb0 = list[it + 2];
            int nb1 = (it + 3 < cnt) ? list[it + 3] : nb0;
            k_ld(nb0, nb1);
        }

        // ---- QK MMA (always; every warp owns keys [16w,16w+16) for all rows) ----
        float C[2][2][4];
        #pragma unroll
        for (int mt = 0; mt < 2; mt++)
            #pragma unroll
            for (int nt = 0; nt < 2; nt++)
                #pragma unroll
                for (int e = 0; e < 4; e++) C[mt][nt][e] = 0.f;

        #pragma unroll
        for (int ks = 0; ks < 4; ks++) {
            u32 ahi[2][4], alo[2][4];
            #pragma unroll
            for (int mt = 0; mt < 2; mt++) {
                u32 off = (u32)(((mt*16 + arow)*72 + ks*16 + acol)*2);
                ldmx4(ahi[mt], qhiA + off);
                ldmx4(alo[mt], qloA + off);
            }
            #pragma unroll
            for (int nt = 0; nt < 2; nt++) {
                int key0 = 16*w + 8*nt;
                u32 boff = (u32)(((key0 + brow)*72 + ks*16 + bcol)*2);
                u32 bhi[2], blo[2];
                ldmx2(bhi, khiA + boff);
                ldmx2(blo, kloA + boff);
                #pragma unroll
                for (int mt = 0; mt < 2; mt++) {
                    mma16816(C[mt][nt], ahi[mt], bhi);
                    mma16816(C[mt][nt], ahi[mt], blo);
                    mma16816(C[mt][nt], alo[mt], bhi);
                }
            }
        }

        // ---- p = mask * silu(s*SCALE) * gsv ----
        {
            int kbw = (w < 2) ? kb0 : kb1;
            bool tok = (w < 2) ? true : has1;
            bool diag = (kbw == qb);
            #pragma unroll
            for (int mt = 0; mt < 2; mt++) {
                #pragma unroll
                for (int nt = 0; nt < 2; nt++) {
                    int jl = 16*w + 8*nt + 2*t4;
                    int jt = jl & 31;
                    #pragma unroll
                    for (int hf = 0; hf < 2; hf++) {
                        int r = mt*16 + g4 + hf*8;
                        int jmax = diag ? r : 31;
                        bool selr = tok && ((selm_sh[r] >> kbw) & 1u);
                        float gv = gsv_sh[r];
                        float c0 = C[mt][nt][hf*2 + 0];
                        float c1 = C[mt][nt][hf*2 + 1];
                        float2 pp;
                        pp.x = (selr && (jt     <= jmax)) ? siluf(c0*SCALE)*gv : 0.f;
                        pp.y = (selr && (jt + 1 <= jmax)) ? siluf(c1*SCALE)*gv : 0.f;
                        *(float2*)&p_sh[r*PPITCH + jl] = pp;
                    }
                }
            }
        }
        __syncthreads();

        // ---- PV dim-split scalar fp32 (all warps, all rows) ----
        #pragma unroll
        for (int j4 = 0; j4 < 8; j4++) {
            u64 v0 = vbU[(j4*4 + 0)*32 + 8*w + dp8];
            u64 v1 = vbU[(j4*4 + 1)*32 + 8*w + dp8];
            u64 v2 = vbU[(j4*4 + 2)*32 + 8*w + dp8];
            u64 v3 = vbU[(j4*4 + 3)*32 + 8*w + dp8];
            #pragma unroll
            for (int k = 0; k < 8; k++) {
                float4 pb = p4[(rg + 4*k)*17 + j4];
                acc[k] = ffma2(dup2(pb.x), v0, acc[k]);
                acc[k] = ffma2(dup2(pb.y), v1, acc[k]);
                acc[k] = ffma2(dup2(pb.z), v2, acc[k]);
                acc[k] = ffma2(dup2(pb.w), v3, acc[k]);
            }
        }
        if (has1) {
            #pragma unroll
            for (int j4 = 8; j4 < 16; j4++) {
                u64 v0 = vbU[(j4*4 + 0)*32 + 8*w + dp8];
                u64 v1 = vbU[(j4*4 + 1)*32 + 8*w + dp8];
                u64 v2 = vbU[(j4*4 + 2)*32 + 8*w + dp8];
                u64 v3 = vbU[(j4*4 + 3)*32 + 8*w + dp8];
                #pragma unroll
                for (int k = 0; k < 8; k++) {
                    float4 pb = p4[(rg + 4*k)*17 + j4];
                    acc[k] = ffma2(dup2(pb.x), v0, acc[k]);
                    acc[k] = ffma2(dup2(pb.y), v1, acc[k]);
                    acc[k] = ffma2(dup2(pb.z), v2, acc[k]);
                    acc[k] = ffma2(dup2(pb.w), v3, acc[k]);
                }
            }
        }
        __syncthreads();
    }

    // ================= Output: lane (rg,dp) owns dims (16w+2dp, +1), rows rg+4k ===
    #pragma unroll
    for (int k = 0; k < 8; k++) {
        int r = rg + 4*k;
        if (r < nvalid) {
            float2 o2 = u2f2(acc[k]);
            int n = qb*BSc + r;
            int o = ((t0 + n)*Hc + h)*Dc + 16*w + 2*dp8;
            *(float2*)(out + o) = o2;
        }
    }
}

extern "C" void kernel_launch(void* const* d_in, const int* in_sizes, int n_in,
                              void* d_out, int out_size) {
    const float* pq   = (const float*)d_in[4];
    const float* pk   = (const float*)d_in[5];
    const float* pv   = (const float*)d_in[6];
    const int*   xoff = (const int*)d_in[7];
    const float* gw   = (const float*)d_in[8];
    float* out = (float*)d_out;

    static int configured = 0;
    if (!configured) {
        cudaFuncSetAttribute(hstu_main,
                             cudaFuncAttributeMaxDynamicSharedMemorySize, SMEM_TOT);
        configured = 1;
    }

    prep<<<256 + TOT/256, 256>>>(pk, pv);
    dim3 grid(NBc, Hc, Bc);
    hstu_main<<<grid, 128, SMEM_TOT>>>(pq, pv, gw, xoff, out);
}

// round 17
// speedup vs baseline: 1.2507x; 1.0219x over previous
#include <cuda_runtime.h>
#include <cuda_bf16.h>
#include <math.h>

#define Bc 4
#define Nc 1024
#define Hc 8
#define Dc 64
#define BSc 32
#define NBc 32
#define STOP 16
#define SCALE 0.125f
#define TOT (Bc*Nc*Hc*Dc)
#define CTOT (Bc*NBc*Hc*Dc)
#define PPITCH 68

// dynamic shared layout (bytes); bf16 rows pitch 72 elems = 144B
#define OFF_QP 0          // Phase B: qhi(4608)+qlo(4608); Phase A: kcmp fp32 (8192)
#define OFF_KP 9216       // Phase B: khi(4608)+klo(4608);  Phase A: q fp32 (8192)
#define OFF_V  18432      // vb4 fp32 32 keys (8192)
#define OFF_P  26624      // p_sh 32xPPITCH fp32 (8704)
#define SMEM_TOT 35328

typedef unsigned long long u64;
typedef unsigned int u32;

__device__ float g_kcmp[CTOT];
__device__ float g_vcmp[CTOT];
__device__ __nv_bfloat16 g_khi[TOT], g_klo[TOT];

__device__ __forceinline__ float siluf(float s) {
    return s / (1.f + __expf(-s));
}
__device__ __forceinline__ u64 ffma2(u64 a, u64 b, u64 c) {
    u64 d;
    asm("fma.rn.f32x2 %0, %1, %2, %3;" : "=l"(d) : "l"(a), "l"(b), "l"(c));
    return d;
}
__device__ __forceinline__ u64 dup2(float x) {
    u64 r;
    asm("mov.b64 %0, {%1, %1};" : "=l"(r) : "f"(x));
    return r;
}
__device__ __forceinline__ float2 u2f2(u64 u) {
    float2 f;
    asm("mov.b64 {%0, %1}, %2;" : "=f"(f.x), "=f"(f.y) : "l"(u));
    return f;
}
__device__ __forceinline__ void ldmx4(u32* a, u32 addr) {
    asm volatile("ldmatrix.sync.aligned.m8n8.x4.shared.b16 {%0,%1,%2,%3}, [%4];"
        : "=r"(a[0]), "=r"(a[1]), "=r"(a[2]), "=r"(a[3]) : "r"(addr));
}
__device__ __forceinline__ void ldmx2(u32* b, u32 addr) {
    asm volatile("ldmatrix.sync.aligned.m8n8.x2.shared.b16 {%0,%1}, [%2];"
        : "=r"(b[0]), "=r"(b[1]) : "r"(addr));
}
__device__ __forceinline__ void mma16816(float* c, const u32* a, const u32* b) {
    asm volatile("mma.sync.aligned.m16n8k16.row.col.f32.bf16.bf16.f32 "
        "{%0,%1,%2,%3},{%4,%5,%6,%7},{%8,%9},{%0,%1,%2,%3};"
        : "+f"(c[0]), "+f"(c[1]), "+f"(c[2]), "+f"(c[3])
        : "r"(a[0]), "r"(a[1]), "r"(a[2]), "r"(a[3]), "r"(b[0]), "r"(b[1]));
}

// fused preprocessing: blocks [0,256) block-mean K/V; blocks [256,8448) split K
__global__ void prep(const float* __restrict__ pk, const float* __restrict__ pv) {
    int blk = blockIdx.x;
    if (blk < 256) {
        int o = blk*256 + threadIdx.x;
        int d  = o & 63;
        int h  = (o >> 6) & 7;
        int kb = (o >> 9) & 31;
        int b  = o >> 14;
        float sk = 0.f, sv = 0.f;
        int base = ((b*Nc + kb*BSc)*Hc + h)*Dc + d;
        #pragma unroll 8
        for (int j = 0; j < BSc; j++) {
            sk += pk[base + j*Hc*Dc];
            sv += pv[base + j*Hc*Dc];
        }
        g_kcmp[o] = sk * (1.f/BSc);
        g_vcmp[o] = sv * (1.f/BSc);
    } else {
        int i = (blk - 256)*256 + threadIdx.x;
        float y = pk[i];
        __nv_bfloat16 h2 = __float2bfloat16(y);
        g_khi[i] = h2;
        g_klo[i] = __float2bfloat16(y - __bfloat162float(h2));
    }
}

// CTA = (q_block, head, batch); 4 warps; 5 CTAs/SM.
// Phase A scalar fp32 (exact top-k, gates, compressed PV dim-split).
// Phase B single 32-key tiles: QK bf16-split MMA (warp w owns keys [8w,8w+8)),
// PV dim-split scalar fp32 (warp w owns dims [16w,16w+16)).
__global__ __launch_bounds__(128, 5) void hstu_main(
    const float* __restrict__ pq, const float* __restrict__ pvv,
    const float* __restrict__ gate_w, const int* __restrict__ xoff,
    float* __restrict__ out)
{
    extern __shared__ __align__(16) char smem[];
    float*  qsA   = (float*) (smem + OFF_KP);
    float4* kcmpA = (float4*)(smem + OFF_QP);
    float4* vb4   = (float4*)(smem + OFF_V);
    float*  p_sh  = (float*) (smem + OFF_P);
    __shared__ int list[33];
    __shared__ int lcnt;
    __shared__ unsigned unionm;
    __shared__ unsigned selm_sh[32];
    __shared__ float gsv_sh[32];

    int qb = (NBc - 1) - blockIdx.x;
    int h = blockIdx.y, b = blockIdx.z;
    int len = xoff[b+1] - xoff[b];
    if (qb * BSc >= len) return;
    int nvalid = len - qb*BSc; if (nvalid > BSc) nvalid = BSc;
    int t0 = xoff[b];
    int tid = threadIdx.x, lane = tid & 31, w = tid >> 5;
    int dp8 = lane & 7, rg = lane >> 3;

    const ulonglong2* qshU = (const ulonglong2*)qsA;
    const ulonglong2* kcU  = (const ulonglong2*)kcmpA;
    const u64*        vbU  = (const u64*)vb4;
    const float4*     p4   = (const float4*)p_sh;
    u32 sbase = (u32)__cvta_generic_to_shared(smem);
    u32 qhiA = sbase + OFF_QP, qloA = qhiA + 4608;
    u32 khiA = sbase + OFF_KP, kloA = khiA + 4608;

    // ---- Phase A staging ----
    #pragma unroll
    for (int i = tid; i < 512; i += 128) {
        int r = i >> 4, c4 = i & 15;
        ((float4*)qsA)[r*16 + c4] = ((const float4*)(pq + ((b*Nc + qb*BSc + r)*Hc + h)*Dc))[c4];
        int gc = ((b*NBc + r)*Hc + h)*Dc;
        kcmpA[c4*32 + (r ^ c4)] = ((const float4*)(g_kcmp + gc))[c4];
        vb4[r*16 + c4]          = ((const float4*)(g_vcmp + gc))[c4];
    }
    if (tid == 0) unionm = 0;
    __syncthreads();

    u64 acc[8] = {0,0,0,0,0,0,0,0};
    unsigned wsel = 0;

    // ================= Phase A (scalar fp32, exact top-k) =================
    {
        const float* gw = gate_w + h*Dc*3;
        float gw0a = gw[(2*lane)*3 + 0], gw0b = gw[(2*lane+1)*3 + 0];
        float gw1a = gw[(2*lane)*3 + 1], gw1b = gw[(2*lane+1)*3 + 1];

        u64 sa[8] = {0,0,0,0,0,0,0,0};
        #pragma unroll
        for (int d4 = 0; d4 < 16; d4++) {
            ulonglong2 k0 = kcU[d4*32 + (lane ^ d4)];
            #pragma unroll
            for (int qi = 0; qi < 8; qi++) {
                ulonglong2 q = qshU[(w + qi*4)*16 + d4];
                sa[qi] = ffma2(q.x, k0.x, sa[qi]);
                sa[qi] = ffma2(q.y, k0.y, sa[qi]);
            }
        }
        bool causal = (lane <= qb);
        #pragma unroll
        for (int qi = 0; qi < 8; qi++) {
            int r = w + qi*4;
            float2 fa = u2f2(sa[qi]);
            float sc = (fa.x + fa.y) * SCALE;
            bool rowok = (r < nvalid);

            float q0 = qsA[r*64 + 2*lane], q1 = qsA[r*64 + 2*lane + 1];
            float pg0 = q0*gw0a + q1*gw0b;
            float pg1 = q0*gw1a + q1*gw1b;
            #pragma unroll
            for (int off = 16; off > 0; off >>= 1) {
                pg0 += __shfl_xor_sync(0xffffffffu, pg0, off);
                pg1 += __shfl_xor_sync(0xffffffffu, pg1, off);
            }
            float gcv = 1.f / (1.f + __expf(-pg0));
            float gsvv = 1.f / (1.f + __expf(-pg1));

            p_sh[r*PPITCH + lane] = (causal && rowok) ? siluf(sc) * gcv : 0.f;

            unsigned sel;
            if (!rowok) {
                sel = 0u;
            } else if (qb < STOP) {
                sel = (1u << (qb + 1)) - 1u;
            } else {
                unsigned ub = __float_as_uint(sc);
                unsigned u = ((int)ub < 0) ? ~ub : (ub | 0x80000000u);
                if (!causal) u = 0u;
                unsigned T = 0u;
                #pragma unroll
                for (int bit = 31; bit >= 0; --bit) {
                    unsigned cand = T | (1u << bit);
                    unsigned bal = __ballot_sync(0xffffffffu, u >= cand);
                    if (__popc(bal) >= STOP) T = cand;
                }
                unsigned gt = __ballot_sync(0xffffffffu, u > T);
                unsigned eq = __ballot_sync(0xffffffffu, u == T);
                int need = STOP - __popc(gt);
                bool take = ((eq >> lane) & 1u) &&
                            (__popc(eq & ((1u << lane) - 1u)) < need);
                unsigned eqt = __ballot_sync(0xffffffffu, take);
                sel = gt | eqt;
            }
            wsel |= sel;
            if (lane == 0) { selm_sh[r] = sel; gsv_sh[r] = gsvv; }
        }
        __syncwarp();
        if (lane == 0) atomicOr(&unionm, wsel);
    }
    __syncthreads();   // p rows + selm + gsv visible

    // ---- compressed PV (dim-split; keys 0..qb) ----
    {
        int j4hi = qb >> 2;
        for (int j4 = 0; j4 <= j4hi; j4++) {
            u64 v0 = vbU[(j4*4 + 0)*32 + 8*w + dp8];
            u64 v1 = vbU[(j4*4 + 1)*32 + 8*w + dp8];
            u64 v2 = vbU[(j4*4 + 2)*32 + 8*w + dp8];
            u64 v3 = vbU[(j4*4 + 3)*32 + 8*w + dp8];
            #pragma unroll
            for (int k = 0; k < 8; k++) {
                float4 pb = p4[(rg + 4*k)*17 + j4];
                acc[k] = ffma2(dup2(pb.x), v0, acc[k]);
                acc[k] = ffma2(dup2(pb.y), v1, acc[k]);
                acc[k] = ffma2(dup2(pb.z), v2, acc[k]);
                acc[k] = ffma2(dup2(pb.w), v3, acc[k]);
            }
        }
    }
    __syncthreads();
    unsigned um = unionm;
    if (tid == 0) {
        int c = 0;
        for (int kb = 0; kb <= qb; kb++)
            if ((um >> kb) & 1u) list[c++] = kb;
        lcnt = c;
    }

    // ---- derive q bf16 planes locally (overwrites kcmp region) ----
    #pragma unroll
    for (int s = 0; s < 2; s++) {
        int i = tid + s*128;
        int row = i >> 3, c = i & 7;
        const float* qr = qsA + row*64 + c*8;
        u32 hw[4], lw[4];
        #pragma unroll
        for (int e = 0; e < 4; e++) {
            float x0 = qr[2*e], x1 = qr[2*e + 1];
            __nv_bfloat16 h0 = __float2bfloat16(x0), h1 = __float2bfloat16(x1);
            __nv_bfloat162 hh2 = {h0, h1};
            hw[e] = *(u32*)&hh2;
            __nv_bfloat162 ll2 = {__float2bfloat16(x0 - __bfloat162float(h0)),
                                  __float2bfloat16(x1 - __bfloat162float(h1))};
            lw[e] = *(u32*)&ll2;
        }
        *(uint4*)(smem + OFF_QP + row*144 + c*16)        = *(uint4*)hw;
        *(uint4*)(smem + OFF_QP + 4608 + row*144 + c*16) = *(uint4*)lw;
    }
    __syncthreads();
    int cnt = lcnt;

    // ================= Phase B: single 32-key tiles =================
    int cst = tid & 7;            // 16B chunk within bf16 row
    int k0t = tid >> 3;           // base key (+16)
    float4 rkhi[2], rklo[2];

    auto k_ld = [&](int kb0) {
        #pragma unroll
        for (int s = 0; s < 2; s++) {
            int key = k0t + s*16;
            int g = ((b*Nc + kb0*BSc + key)*Hc + h)*Dc + cst*8;
            rkhi[s] = *(const float4*)(g_khi + g);
            rklo[s] = *(const float4*)(g_klo + g);
        }
    };
    if (cnt > 0) k_ld(list[0]);

    int r0s = tid >> 4, c4s = tid & 15;
    int arow = ((lane >> 3) & 1)*8 + (lane & 7);
    int acol = (lane >> 4)*8;
    int brow = lane & 7;
    int bcol = ((lane >> 3) & 1)*8;
    int g4 = lane >> 2, t4 = lane & 3;

    for (int it = 0; it < cnt; it++) {
        int kb = list[it];

        // store prefetched K planes; stage V inline
        #pragma unroll
        for (int s = 0; s < 2; s++) {
            int key = k0t + s*16;
            *(float4*)(smem + OFF_KP + key*144 + cst*16)        = rkhi[s];
            *(float4*)(smem + OFF_KP + 4608 + key*144 + cst*16) = rklo[s];
        }
        #pragma unroll
        for (int s = 0; s < 4; s++) {
            int row = r0s + s*8;
            vb4[row*16 + c4s] = ((const float4*)(pvv + ((b*Nc + kb*BSc + row)*Hc + h)*Dc))[c4s];
        }
        __syncthreads();

        if (it + 1 < cnt) k_ld(list[it + 1]);

        // ---- QK MMA: warp w computes keys [8w,8w+8) x rows 0..31 ----
        float C[2][4];
        #pragma unroll
        for (int mt = 0; mt < 2; mt++)
            #pragma unroll
            for (int e = 0; e < 4; e++) C[mt][e] = 0.f;

        #pragma unroll
        for (int ks = 0; ks < 4; ks++) {
            u32 ahi[2][4], alo[2][4];
            #pragma unroll
            for (int mt = 0; mt < 2; mt++) {
                u32 off = (u32)(((mt*16 + arow)*72 + ks*16 + acol)*2);
                ldmx4(ahi[mt], qhiA + off);
                ldmx4(alo[mt], qloA + off);
            }
            int key0 = 8*w;
            u32 boff = (u32)(((key0 + brow)*72 + ks*16 + bcol)*2);
            u32 bhi[2], blo[2];
            ldmx2(bhi, khiA + boff);
            ldmx2(blo, kloA + boff);
            #pragma unroll
            for (int mt = 0; mt < 2; mt++) {
                mma16816(C[mt], ahi[mt], bhi);
                mma16816(C[mt], ahi[mt], blo);
                mma16816(C[mt], alo[mt], bhi);
            }
        }

        // ---- p = mask * silu(s*SCALE) * gsv ----
        {
            bool diag = (kb == qb);
            int jl = 8*w + 2*t4;
            #pragma unroll
            for (int mt = 0; mt < 2; mt++) {
                #pragma unroll
                for (int hf = 0; hf < 2; hf++) {
                    int r = mt*16 + g4 + hf*8;
                    int jmax = diag ? r : 31;
                    bool selr = (selm_sh[r] >> kb) & 1u;
                    float gv = gsv_sh[r];
                    float c0 = C[mt][hf*2 + 0];
                    float c1 = C[mt][hf*2 + 1];
                    float2 pp;
                    pp.x = (selr && (jl     <= jmax)) ? siluf(c0*SCALE)*gv : 0.f;
                    pp.y = (selr && (jl + 1 <= jmax)) ? siluf(c1*SCALE)*gv : 0.f;
                    *(float2*)&p_sh[r*PPITCH + jl] = pp;
                }
            }
        }
        __syncthreads();

        // ---- PV dim-split scalar fp32 ----
        #pragma unroll
        for (int j4 = 0; j4 < 8; j4++) {
            u64 v0 = vbU[(j4*4 + 0)*32 + 8*w + dp8];
            u64 v1 = vbU[(j4*4 + 1)*32 + 8*w + dp8];
            u64 v2 = vbU[(j4*4 + 2)*32 + 8*w + dp8];
            u64 v3 = vbU[(j4*4 + 3)*32 + 8*w + dp8];
            #pragma unroll
            for (int k = 0; k < 8; k++) {
                float4 pb = p4[(rg + 4*k)*17 + j4];
                acc[k] = ffma2(dup2(pb.x), v0, acc[k]);
                acc[k] = ffma2(dup2(pb.y), v1, acc[k]);
                acc[k] = ffma2(dup2(pb.z), v2, acc[k]);
                acc[k] = ffma2(dup2(pb.w), v3, acc[k]);
            }
        }
        __syncthreads();
    }

    // ================= Output: lane (rg,dp) owns dims (16w+2dp, +1), rows rg+4k ===
    #pragma unroll
    for (int k = 0; k < 8; k++) {
        int r = rg + 4*k;
        if (r < nvalid) {
            float2 o2 = u2f2(acc[k]);
            int n = qb*BSc + r;
            int o = ((t0 + n)*Hc + h)*Dc + 16*w + 2*dp8;
            *(float2*)(out + o) = o2;
        }
    }
}

extern "C" void kernel_launch(void* const* d_in, const int* in_sizes, int n_in,
                              void* d_out, int out_size) {
    const float* pq   = (const float*)d_in[4];
    const float* pk   = (const float*)d_in[5];
    const float* pv   = (const float*)d_in[6];
    const int*   xoff = (const int*)d_in[7];
    const float* gw   = (const float*)d_in[8];
    float* out = (float*)d_out;

    static int configured = 0;
    if (!configured) {
        cudaFuncSetAttribute(hstu_main,
                             cudaFuncAttributeMaxDynamicSharedMemorySize, SMEM_TOT);
        configured = 1;
    }

    prep<<<256 + TOT/256, 256>>>(pk, pv);
    dim3 grid(NBc, Hc, Bc);
    hstu_main<<<grid, 128, SMEM_TOT>>>(pq, pv, gw, xoff, out);
}